// round 7
// baseline (speedup 1.0000x reference)
#include <cuda_runtime.h>
#include <cuda_bf16.h>
#include <cstdint>

// ============================================================================
// MajFC:  out = 1.125 * <X", W">  with augmented ±1 vectors (K = 3072 + 1024):
//   per 3-group, clip(sum,-1,1) = 0.5*(x0w0 + x1w1 + x2w2 - (x0x1x2)(w0w1w2)).
// Bit-packed:  out = 4608 - 2.25 * popc(xbits ^ wbits)  over 128 words.
// Bit order is an arbitrary fixed permutation, identical for X and W.
// GEMM is K-split 4 ways for occupancy; exact uint16 partials combined after.
// ============================================================================

#define BROWS 256
#define CIN   3072
#define COUT  1024
#define KW    128            // 4096 bits per row
#define NSPLIT 4
#define KC    (KW / NSPLIT)  // 32 words per split
#define NPO   (BROWS * COUT)

__device__ __align__(16) uint32_t g_Xb[BROWS * KW];               // 128 KB
__device__ __align__(16) uint32_t g_Wb[COUT  * KW];               // 512 KB
__device__ __align__(16) unsigned short g_part[NSPLIT * NPO];     // 2 MB

// ---------------------------------------------------------------------------
// Pack v3: one warp = 768 consecutive floats (256 groups) of one row.
// Lane i: 6x LDG.128 (24 floats) -> 24 sign bits + 8 group-parity bits.
// 32 ballots -> 24 element words + 8 product words; one STG.32 per lane.
// ---------------------------------------------------------------------------
#define SEGS 4                                   // 768-float segments per row
#define PACK_TASKS ((BROWS + COUT) * SEGS)       // 5120 warps

__global__ void __launch_bounds__(256) pack_kernel(const float* __restrict__ x,
                                                   const float* __restrict__ w) {
    int task = (blockIdx.x * blockDim.x + threadIdx.x) >> 5;
    int lane = threadIdx.x & 31;

    int row = task >> 2, seg = task & 3;
    const float* src;
    uint32_t*    dst;
    unsigned flip;
    if (row < BROWS) {
        src = x + (size_t)row * CIN;
        dst = g_Xb + (size_t)row * KW;
        flip = 0u;
    } else {
        src = w + (size_t)(row - BROWS) * CIN;
        dst = g_Wb + (size_t)(row - BROWS) * KW;
        flip = 1u;                       // -prod(W) folded into the bit
    }

    const float4* p = reinterpret_cast<const float4*>(src + seg * 768 + lane * 24);
    float f[24];
#pragma unroll
    for (int j = 0; j < 6; j++) {
        float4 v = p[j];
        f[j * 4 + 0] = v.x; f[j * 4 + 1] = v.y;
        f[j * 4 + 2] = v.z; f[j * 4 + 3] = v.w;
    }
    unsigned b[24];
#pragma unroll
    for (int j = 0; j < 24; j++) b[j] = f[j] > 0.f;

    unsigned myword = 0;
#pragma unroll
    for (int j = 0; j < 24; j++) {               // element words
        unsigned bw = __ballot_sync(0xFFFFFFFFu, b[j]);
        if (lane == j) myword = bw;
    }
#pragma unroll
    for (int g = 0; g < 8; g++) {                // product (parity) words
        unsigned pb = b[3 * g] ^ b[3 * g + 1] ^ b[3 * g + 2] ^ flip;
        unsigned bw = __ballot_sync(0xFFFFFFFFu, pb);
        if (lane == 24 + g) myword = bw;
    }

    if (lane < 24) dst[seg * 24 + lane]       = myword;   // region 1: 96 words
    else           dst[96 + seg * 8 + lane - 24] = myword; // region 2: 32 words
}

// ---------------------------------------------------------------------------
// Binary GEMM, K-split: CTA tile 32(m) x 16(n) over one 32-word K chunk.
// 128 threads, thread tile 2x2. grid = (64, 8, 4) = 2048 CTAs.
// Pitch 36 words = 144 B: every row base is 16B-aligned -> LDS.128 legal.
// ---------------------------------------------------------------------------
#define GM 32
#define GN 16
#define SP 36

__global__ void __launch_bounds__(128, 10) maj_gemm_kernel() {
    __shared__ __align__(16) uint32_t Xs[GM][SP];   // 4.5 KB
    __shared__ __align__(16) uint32_t Ws[GN][SP];   // 2.25 KB

    int tid = threadIdx.x;
    int n0 = blockIdx.x * GN;         // 64
    int m0 = blockIdx.y * GM;         // 8
    int sp = blockIdx.z;              // 4
    int k0 = sp * KC;

    // Stage: 48 rows x 32 words = 384 uint4, 3 per thread.
#pragma unroll
    for (int p = 0; p < 3; p++) {
        int idx = p * 128 + tid;
        int row = idx >> 3, c = (idx & 7) << 2;
        const uint32_t* src = (row < GM)
            ? &g_Xb[(size_t)(m0 + row) * KW + k0 + c]
            : &g_Wb[(size_t)(n0 + row - GM) * KW + k0 + c];
        uint4 v = *reinterpret_cast<const uint4*>(src);
        uint32_t* d = (row < GM) ? &Xs[row][c] : &Ws[row - GM][c];
        *reinterpret_cast<uint4*>(d) = v;
    }
    __syncthreads();

    int mi = tid >> 3;                // 0..15 -> m rows 2mi, 2mi+1
    int ni = tid & 7;                 // 0..7  -> n rows 2ni, 2ni+1
    const uint32_t* xa = &Xs[mi * 2][0];
    const uint32_t* xb = &Xs[mi * 2 + 1][0];
    const uint32_t* wa = &Ws[ni * 2][0];
    const uint32_t* wb = &Ws[ni * 2 + 1][0];

    int a00 = 0, a01 = 0, a10 = 0, a11 = 0;
#pragma unroll
    for (int k = 0; k < KC; k += 4) {
        uint4 x0 = *reinterpret_cast<const uint4*>(&xa[k]);
        uint4 x1 = *reinterpret_cast<const uint4*>(&xb[k]);
        uint4 v0 = *reinterpret_cast<const uint4*>(&wa[k]);
        uint4 v1 = *reinterpret_cast<const uint4*>(&wb[k]);
        a00 += __popc(x0.x ^ v0.x) + __popc(x0.y ^ v0.y)
             + __popc(x0.z ^ v0.z) + __popc(x0.w ^ v0.w);
        a01 += __popc(x0.x ^ v1.x) + __popc(x0.y ^ v1.y)
             + __popc(x0.z ^ v1.z) + __popc(x0.w ^ v1.w);
        a10 += __popc(x1.x ^ v0.x) + __popc(x1.y ^ v0.y)
             + __popc(x1.z ^ v0.z) + __popc(x1.w ^ v0.w);
        a11 += __popc(x1.x ^ v1.x) + __popc(x1.y ^ v1.y)
             + __popc(x1.z ^ v1.z) + __popc(x1.w ^ v1.w);
    }

    // Counts <= 1024 -> uint16 partials (halves combine traffic).
    int m = m0 + mi * 2, n = n0 + ni * 2;
    unsigned short* pb = g_part + (size_t)sp * NPO + (size_t)m * COUT + n;
    *reinterpret_cast<ushort2*>(pb) =
        make_ushort2((unsigned short)a00, (unsigned short)a01);
    *reinterpret_cast<ushort2*>(pb + COUT) =
        make_ushort2((unsigned short)a10, (unsigned short)a11);
}

// ---------------------------------------------------------------------------
// Combine: out = 4608 - 2.25 * (p0+p1+p2+p3).
// ---------------------------------------------------------------------------
__global__ void combine_kernel(float* __restrict__ out) {
    int i = (blockIdx.x * blockDim.x + threadIdx.x) << 2;
    ushort4 a = *reinterpret_cast<const ushort4*>(&g_part[i]);
    ushort4 b = *reinterpret_cast<const ushort4*>(&g_part[NPO + i]);
    ushort4 c = *reinterpret_cast<const ushort4*>(&g_part[2 * NPO + i]);
    ushort4 d = *reinterpret_cast<const ushort4*>(&g_part[3 * NPO + i]);
    float4 o;
    o.x = 4608.0f - 2.25f * (float)(a.x + b.x + c.x + d.x);
    o.y = 4608.0f - 2.25f * (float)(a.y + b.y + c.y + d.y);
    o.z = 4608.0f - 2.25f * (float)(a.z + b.z + c.z + d.z);
    o.w = 4608.0f - 2.25f * (float)(a.w + b.w + c.w + d.w);
    *reinterpret_cast<float4*>(&out[i]) = o;
}

// ---------------------------------------------------------------------------
extern "C" void kernel_launch(void* const* d_in, const int* in_sizes, int n_in,
                              void* d_out, int out_size) {
    const float* x = (const float*)d_in[0];   // [256, 3072]
    const float* w = (const float*)d_in[1];   // [1024, 3072]
    float* out = (float*)d_out;               // [256, 1024] float32

    pack_kernel<<<PACK_TASKS * 32 / 256, 256>>>(x, w);

    dim3 grid(COUT / GN, BROWS / GM, NSPLIT); // (64, 8, 4) = 2048 CTAs
    maj_gemm_kernel<<<grid, 128>>>();

    combine_kernel<<<NPO / (256 * 4), 256>>>(out);
}

// round 8
// speedup vs baseline: 1.0152x; 1.0152x over previous
#include <cuda_runtime.h>
#include <cuda_bf16.h>
#include <cstdint>

// ============================================================================
// MajFC:  out = 1.125 * <X", W">  with augmented ±1 vectors (K = 3072 + 1024):
//   per 3-group, clip(sum,-1,1) = 0.5*(x0w0 + x1w1 + x2w2 - (x0x1x2)(w0w1w2)).
// Bit-packed:  out = 4608 - 2.25 * popc(xbits ^ wbits)  over 128 words.
// K-split-4 GEMM; combine FUSED via per-tile atomic finisher (2 launches total).
// ============================================================================

#define BROWS 256
#define CIN   3072
#define COUT  1024
#define KW    128            // 4096 bits per row
#define NSPLIT 4
#define KC    (KW / NSPLIT)  // 32 words per split
#define NPO   (BROWS * COUT)

__device__ __align__(16) uint32_t g_Xb[BROWS * KW];               // 128 KB
__device__ __align__(16) uint32_t g_Wb[COUT  * KW];               // 512 KB
__device__ __align__(16) unsigned short g_part[NSPLIT * NPO];     // 2 MB
__device__ int g_cnt[512];                                        // zero-init

// ---------------------------------------------------------------------------
// Pack: one warp = 768 consecutive floats (256 groups) of one row.
// ---------------------------------------------------------------------------
#define SEGS 4
#define PACK_TASKS ((BROWS + COUT) * SEGS)       // 5120 warps

__global__ void __launch_bounds__(256) pack_kernel(const float* __restrict__ x,
                                                   const float* __restrict__ w) {
    int task = (blockIdx.x * blockDim.x + threadIdx.x) >> 5;
    int lane = threadIdx.x & 31;

    int row = task >> 2, seg = task & 3;
    const float* src;
    uint32_t*    dst;
    unsigned flip;
    if (row < BROWS) {
        src = x + (size_t)row * CIN;
        dst = g_Xb + (size_t)row * KW;
        flip = 0u;
    } else {
        src = w + (size_t)(row - BROWS) * CIN;
        dst = g_Wb + (size_t)(row - BROWS) * KW;
        flip = 1u;                       // -prod(W) folded into the bit
    }

    const float4* p = reinterpret_cast<const float4*>(src + seg * 768 + lane * 24);
    float f[24];
#pragma unroll
    for (int j = 0; j < 6; j++) {
        float4 v = p[j];
        f[j * 4 + 0] = v.x; f[j * 4 + 1] = v.y;
        f[j * 4 + 2] = v.z; f[j * 4 + 3] = v.w;
    }
    unsigned b[24];
#pragma unroll
    for (int j = 0; j < 24; j++) b[j] = f[j] > 0.f;

    unsigned myword = 0;
#pragma unroll
    for (int j = 0; j < 24; j++) {               // element words
        unsigned bw = __ballot_sync(0xFFFFFFFFu, b[j]);
        if (lane == j) myword = bw;
    }
#pragma unroll
    for (int g = 0; g < 8; g++) {                // product (parity) words
        unsigned pb = b[3 * g] ^ b[3 * g + 1] ^ b[3 * g + 2] ^ flip;
        unsigned bw = __ballot_sync(0xFFFFFFFFu, pb);
        if (lane == 24 + g) myword = bw;
    }

    if (lane < 24) dst[seg * 24 + lane]          = myword;   // region 1
    else           dst[96 + seg * 8 + lane - 24] = myword;   // region 2
}

// ---------------------------------------------------------------------------
// Binary GEMM, K-split + fused combine. CTA tile 32(m) x 16(n), one 32-word
// K chunk, 128 threads, thread tile 2x2. grid = (4, 64, 8); sp fastest so the
// 4 split-CTAs of a tile launch adjacently (finisher fires promptly).
// Pitch 36 words = 144 B: every row 16B-aligned -> LDS.128 legal.
// ---------------------------------------------------------------------------
#define GM 32
#define GN 16
#define SP 36

__global__ void __launch_bounds__(128, 10) maj_gemm_kernel(float* __restrict__ out) {
    __shared__ __align__(16) uint32_t Xs[GM][SP];
    __shared__ __align__(16) uint32_t Ws[GN][SP];
    __shared__ int s_last;

    int tid = threadIdx.x;
    int sp = blockIdx.x;              // 4
    int n0 = blockIdx.y * GN;         // 64
    int m0 = blockIdx.z * GM;         // 8
    int tile = blockIdx.z * 64 + blockIdx.y;   // 0..511
    int k0 = sp * KC;

    // Stage: 48 rows x 32 words = 384 uint4, 3 per thread.
#pragma unroll
    for (int p = 0; p < 3; p++) {
        int idx = p * 128 + tid;
        int row = idx >> 3, c = (idx & 7) << 2;
        const uint32_t* src = (row < GM)
            ? &g_Xb[(size_t)(m0 + row) * KW + k0 + c]
            : &g_Wb[(size_t)(n0 + row - GM) * KW + k0 + c];
        uint4 v = *reinterpret_cast<const uint4*>(src);
        uint32_t* d = (row < GM) ? &Xs[row][c] : &Ws[row - GM][c];
        *reinterpret_cast<uint4*>(d) = v;
    }
    __syncthreads();

    int mi = tid >> 3;                // 0..15 -> m rows 2mi, 2mi+1
    int ni = tid & 7;                 // 0..7  -> n rows 2ni, 2ni+1
    const uint32_t* xa = &Xs[mi * 2][0];
    const uint32_t* xb = &Xs[mi * 2 + 1][0];
    const uint32_t* wa = &Ws[ni * 2][0];
    const uint32_t* wb = &Ws[ni * 2 + 1][0];

    int a00 = 0, a01 = 0, a10 = 0, a11 = 0;
#pragma unroll
    for (int k = 0; k < KC; k += 4) {
        uint4 x0 = *reinterpret_cast<const uint4*>(&xa[k]);
        uint4 x1 = *reinterpret_cast<const uint4*>(&xb[k]);
        uint4 v0 = *reinterpret_cast<const uint4*>(&wa[k]);
        uint4 v1 = *reinterpret_cast<const uint4*>(&wb[k]);
        a00 += __popc(x0.x ^ v0.x) + __popc(x0.y ^ v0.y)
             + __popc(x0.z ^ v0.z) + __popc(x0.w ^ v0.w);
        a01 += __popc(x0.x ^ v1.x) + __popc(x0.y ^ v1.y)
             + __popc(x0.z ^ v1.z) + __popc(x0.w ^ v1.w);
        a10 += __popc(x1.x ^ v0.x) + __popc(x1.y ^ v0.y)
             + __popc(x1.z ^ v0.z) + __popc(x1.w ^ v0.w);
        a11 += __popc(x1.x ^ v1.x) + __popc(x1.y ^ v1.y)
             + __popc(x1.z ^ v1.z) + __popc(x1.w ^ v1.w);
    }

    // Counts <= 1024 -> uint16 partials.
    int m = m0 + mi * 2, n = n0 + ni * 2;
    unsigned short* pb = g_part + (size_t)sp * NPO + (size_t)m * COUT + n;
    *reinterpret_cast<ushort2*>(pb) =
        make_ushort2((unsigned short)a00, (unsigned short)a01);
    *reinterpret_cast<ushort2*>(pb + COUT) =
        make_ushort2((unsigned short)a10, (unsigned short)a11);

    // ---- fused combine: 4th-arriving split-CTA finishes the tile ----
    __threadfence();                  // partials visible gpu-wide
    __syncthreads();
    if (tid == 0) s_last = atomicAdd(&g_cnt[tile], 1);
    __syncthreads();
    if (s_last == NSPLIT - 1) {
        // 512 outputs, 4 per thread: m-row = tid>>2, n-quad = (tid&3)*4
        int fm = m0 + (tid >> 2);
        int fn = n0 + (tid & 3) * 4;
        size_t off = (size_t)fm * COUT + fn;
        ushort4 p0 = *reinterpret_cast<const ushort4*>(&g_part[off]);
        ushort4 p1 = *reinterpret_cast<const ushort4*>(&g_part[NPO + off]);
        ushort4 p2 = *reinterpret_cast<const ushort4*>(&g_part[2 * NPO + off]);
        ushort4 p3 = *reinterpret_cast<const ushort4*>(&g_part[3 * NPO + off]);
        float4 o;
        o.x = 4608.0f - 2.25f * (float)(p0.x + p1.x + p2.x + p3.x);
        o.y = 4608.0f - 2.25f * (float)(p0.y + p1.y + p2.y + p3.y);
        o.z = 4608.0f - 2.25f * (float)(p0.z + p1.z + p2.z + p3.z);
        o.w = 4608.0f - 2.25f * (float)(p0.w + p1.w + p2.w + p3.w);
        *reinterpret_cast<float4*>(&out[off]) = o;
        if (tid == 0) g_cnt[tile] = 0;   // reset for next graph replay
    }
}

// ---------------------------------------------------------------------------
extern "C" void kernel_launch(void* const* d_in, const int* in_sizes, int n_in,
                              void* d_out, int out_size) {
    const float* x = (const float*)d_in[0];   // [256, 3072]
    const float* w = (const float*)d_in[1];   // [1024, 3072]
    float* out = (float*)d_out;               // [256, 1024] float32

    pack_kernel<<<PACK_TASKS * 32 / 256, 256>>>(x, w);

    dim3 grid(NSPLIT, COUT / GN, BROWS / GM); // (4, 64, 8) = 2048 CTAs
    maj_gemm_kernel<<<grid, 128>>>(out);
}